// round 4
// baseline (speedup 1.0000x reference)
#include <cuda_runtime.h>
#include <math.h>

#define Bdim 16
#define Sdim 1024
#define Ddim 512
#define Hdim 8
#define DHdim 64

// ---------------- scratch ----------------
__device__ float g_w    [5*Ddim*Ddim];              // tf32-rounded weights
__device__ float g_conv [Bdim*Ddim*Sdim];
__device__ float g_n1   [Bdim*Ddim*Sdim];
__device__ float g_dense[Bdim*Ddim*Sdim];
__device__ float g_q    [Bdim*Ddim*Sdim];           // (b, h*64+c, s)
__device__ float g_kt   [Bdim*Hdim*Sdim*DHdim];     // (b,h,s,c)
__device__ float g_vt   [Bdim*Hdim*Sdim*DHdim];     // (b,h,s,c)
__device__ float g_cat  [Bdim*Ddim*Sdim];
__device__ float g_sc   [(size_t)Bdim*Hdim*Sdim*Sdim]; // scT[bh][j][i]
__device__ float g_pmax [Bdim*Hdim*Sdim*64];        // per-16-chunk causal row max
__device__ float g_rinv [Bdim*Hdim*Sdim];

// ---------------- helpers ----------------
__device__ __forceinline__ float warp_sum(float v){
    #pragma unroll
    for(int o=16;o;o>>=1) v += __shfl_xor_sync(0xffffffffu, v, o);
    return v;
}
__device__ __forceinline__ float warp_max(float v){
    #pragma unroll
    for(int o=16;o;o>>=1) v = fmaxf(v, __shfl_xor_sync(0xffffffffu, v, o));
    return v;
}
__device__ __forceinline__ float f2tf(float x){
    unsigned r; asm("cvt.rna.tf32.f32 %0, %1;" : "=r"(r) : "f"(x));
    return __uint_as_float(r);
}
__device__ __forceinline__ void mma8(float* d, const unsigned* a, const unsigned* b){
    asm volatile(
      "mma.sync.aligned.m16n8k8.row.col.f32.tf32.tf32.f32 "
      "{%0,%1,%2,%3}, {%4,%5,%6,%7}, {%8,%9}, {%0,%1,%2,%3};\n"
      : "+f"(d[0]), "+f"(d[1]), "+f"(d[2]), "+f"(d[3])
      : "r"(a[0]), "r"(a[1]), "r"(a[2]), "r"(a[3]), "r"(b[0]), "r"(b[1]));
}
// permuted-k A layout: 16 floats per row; element (row, k) at pos (k&3)*4+(k>>2),
// XOR-swizzled by row parity bits. returns float offset.
__device__ __forceinline__ int aswz(int row, int p){
    return row*16 + (p ^ ((row&1)*8) ^ (((row>>1)&1)*4));
}

// ============ Kernel 0: round weights to tf32 once ==========================
__global__ void k_prep(const float* __restrict__ Mw, const float* __restrict__ Wq,
                       const float* __restrict__ Wk, const float* __restrict__ Wv,
                       const float* __restrict__ Wo)
{
    int idx = (blockIdx.x*256 + threadIdx.x)*4;
    int w = idx >> 18, off = idx & 262143;
    const float* src = (w==0)?Mw:(w==1)?Wq:(w==2)?Wk:(w==3)?Wv:Wo;
    float4 v = *(const float4*)&src[off];
    v.x=f2tf(v.x); v.y=f2tf(v.y); v.z=f2tf(v.z); v.w=f2tf(v.w);
    *(float4*)&g_w[idx] = v;
}

// ============ Kernel 1: conv + pe + gelu + LN1 ==============================
__global__ void k_front(const float* __restrict__ ts, const float* __restrict__ cw,
                        const float* __restrict__ cb, const float* __restrict__ pe,
                        const float* __restrict__ g1, const float* __restrict__ b1)
{
    __shared__ float sm[16][513];
    int b = blockIdx.y, s0 = blockIdx.x*16;
    int tid = threadIdx.x;
    int d = tid;
    float w0=cw[d*4+0], w1=cw[d*4+1], w2=cw[d*4+2], w3=cw[d*4+3];
    float bias = cb[d];
    const float* tsb = ts + b*4096;
    #pragma unroll
    for(int sl=0; sl<16; ++sl){
        int s = s0+sl;
        sm[sl][d] = bias + pe[s*Ddim + d]
                  + tsb[s*4+0]*w0 + tsb[s*4+1]*w1 + tsb[s*4+2]*w2 + tsb[s*4+3]*w3;
    }
    __syncthreads();
    float* convp = g_conv + (size_t)b*Ddim*Sdim;
    #pragma unroll
    for(int it=0; it<16; ++it){
        int idx = it*512 + tid; int sl = idx & 15, dd = idx >> 4;
        convp[(size_t)dd*Sdim + s0 + sl] = sm[sl][dd];
    }
    __syncthreads();
    #pragma unroll
    for(int sl=0; sl<16; ++sl){
        float x = sm[sl][d];
        sm[sl][d] = 0.5f*x*(1.0f + erff(x*0.70710678118654752f));
    }
    __syncthreads();
    int wrp = tid>>5, lane = tid&31;
    {
        float sum=0.f, sq=0.f;
        #pragma unroll
        for(int k=0;k<16;k++){ float x = sm[wrp][lane + k*32]; sum+=x; sq+=x*x; }
        sum = warp_sum(sum); sq = warp_sum(sq);
        float mean = sum*(1.0f/512.0f);
        float var  = (sq - 512.0f*mean*mean)*(1.0f/511.0f);
        float inv  = rsqrtf(var + 1e-5f);
        float gg = g1[s0+wrp], bb = b1[s0+wrp];
        #pragma unroll
        for(int k=0;k<16;k++){
            int dd = lane + k*32;
            sm[wrp][dd] = (sm[wrp][dd]-mean)*inv*gg + bb;
        }
    }
    __syncthreads();
    float* n1p = g_n1 + (size_t)b*Ddim*Sdim;
    #pragma unroll
    for(int it=0; it<16; ++it){
        int idx = it*512 + tid; int sl = idx & 15, dd = idx >> 4;
        n1p[(size_t)dd*Sdim + s0 + sl] = f2tf(sm[sl][dd]);
    }
}

// ============ tf32 MMA GEMM 128x128x16, permuted-A smem =====================
// modes: 0 dense(+emb) 1 q 2 k->g_kt 3 v->g_vt 4 wo(+bias ->out)
__global__ __launch_bounds__(256) void gemm_tf32(
    float* __restrict__ Cout, const float* __restrict__ bias,
    const float* __restrict__ tsemb, const int* __restrict__ te, int mode)
{
    __shared__ float As[2][128*16];
    __shared__ float Bs[2][16][136];
    int b = blockIdx.z;
    int n0 = blockIdx.x*128, m0 = blockIdx.y*128;
    int wsel = (mode==4) ? 4 : mode;
    const float* W = g_w + (size_t)wsel*262144;
    const float* Bsel = (mode==0) ? g_n1 : (mode==4 ? g_cat : g_dense);
    const float* Bm = Bsel + (size_t)b*Ddim*Sdim;

    int tid = threadIdx.x, lane = tid&31, wid = tid>>5;
    int wm = wid&1, wn = wid>>1;
    int am = tid>>2, akq = (tid&3)*4, ap = akq>>2;
    int bk = tid>>4, bnq = (tid&15)*8;
    int rA = lane>>2, cL = lane&3;

    float4 pa0 = *(const float4*)&W[(size_t)(m0+am)*512 + akq];
    float4 pa1 = *(const float4*)&W[(size_t)(m0+am+64)*512 + akq];
    float4 pb0 = *(const float4*)&Bm[(size_t)bk*Sdim + n0+bnq];
    float4 pb1 = *(const float4*)&Bm[(size_t)bk*Sdim + n0+bnq+4];

    float acc[4][4][4];
    #pragma unroll
    for(int i=0;i<4;i++)
      #pragma unroll
      for(int j=0;j<4;j++)
        #pragma unroll
        for(int k=0;k<4;k++) acc[i][j][k]=0.f;

    int st = 0;
    for(int k0=0;;){
        As[st][aswz(am,     0+ap)] = pa0.x;
        As[st][aswz(am,     4+ap)] = pa0.y;
        As[st][aswz(am,     8+ap)] = pa0.z;
        As[st][aswz(am,    12+ap)] = pa0.w;
        As[st][aswz(am+64,  0+ap)] = pa1.x;
        As[st][aswz(am+64,  4+ap)] = pa1.y;
        As[st][aswz(am+64,  8+ap)] = pa1.z;
        As[st][aswz(am+64, 12+ap)] = pa1.w;
        *(float4*)&Bs[st][bk][bnq]   = pb0;
        *(float4*)&Bs[st][bk][bnq+4] = pb1;
        __syncthreads();
        k0 += 16;
        bool more = (k0 < 512);
        if(more){
            pa0 = *(const float4*)&W[(size_t)(m0+am)*512 + k0+akq];
            pa1 = *(const float4*)&W[(size_t)(m0+am+64)*512 + k0+akq];
            pb0 = *(const float4*)&Bm[(size_t)(k0+bk)*Sdim + n0+bnq];
            pb1 = *(const float4*)&Bm[(size_t)(k0+bk)*Sdim + n0+bnq+4];
        }
        // B fragments (standard layout, scalar)
        unsigned bf0[4][2], bf8[4][2];
        #pragma unroll
        for(int nt=0;nt<4;nt++){
            int n = wn*32 + nt*8 + rA;
            bf0[nt][0] = __float_as_uint(Bs[st][cL   ][n]);
            bf0[nt][1] = __float_as_uint(Bs[st][cL+4 ][n]);
            bf8[nt][0] = __float_as_uint(Bs[st][cL+8 ][n]);
            bf8[nt][1] = __float_as_uint(Bs[st][cL+12][n]);
        }
        // A fragments: one float4 per row gives both kk halves
        #pragma unroll
        for(int mt=0;mt<4;mt++){
            int m = wm*64 + mt*16 + rA;
            float4 a1 = *(const float4*)&As[st][aswz(m,   4*cL)];
            float4 a2 = *(const float4*)&As[st][aswz(m+8, 4*cL)];
            unsigned af0[4] = {__float_as_uint(a1.x), __float_as_uint(a2.x),
                               __float_as_uint(a1.y), __float_as_uint(a2.y)};
            unsigned af8[4] = {__float_as_uint(a1.z), __float_as_uint(a2.z),
                               __float_as_uint(a1.w), __float_as_uint(a2.w)};
            #pragma unroll
            for(int nt=0;nt<4;nt++){
                mma8(acc[mt][nt], af0, bf0[nt]);
                mma8(acc[mt][nt], af8, bf8[nt]);
            }
        }
        st ^= 1;
        if(!more) break;
    }

    const float* embp = (mode==0) ? (tsemb + (size_t)te[b]*512) : 0;

    if(mode==2 || mode==3){
        float* dst = (mode==2) ? g_kt : g_vt;
        #pragma unroll
        for(int mt=0;mt<4;mt++){
            #pragma unroll
            for(int h2=0;h2<2;h2++){
                int r = m0 + wm*64 + mt*16 + rA + h2*8;     // d = h*64+c
                int h = r>>6, c = r&63;
                float* tp = dst + (((size_t)b*Hdim + h)*Sdim)*DHdim + c;
                #pragma unroll
                for(int nt=0;nt<4;nt++){
                    int col = n0 + wn*32 + nt*8 + 2*cL;     // s
                    tp[(size_t)col*DHdim]     = f2tf(acc[mt][nt][h2*2+0]);
                    tp[(size_t)(col+1)*DHdim] = f2tf(acc[mt][nt][h2*2+1]);
                }
            }
        }
        return;
    }

    float* Csel = (mode==0) ? g_dense : (mode==1 ? g_q : Cout);
    float* C = Csel + (size_t)b*Ddim*Sdim;
    #pragma unroll
    for(int mt=0;mt<4;mt++){
        #pragma unroll
        for(int h2=0;h2<2;h2++){
            int r = m0 + wm*64 + mt*16 + rA + h2*8;
            float addv = 0.f;
            if(mode==0) addv = embp[r];
            else if(mode==4) addv = bias[r];
            #pragma unroll
            for(int nt=0;nt<4;nt++){
                int col = n0 + wn*32 + nt*8 + 2*cL;
                float2 v;
                if(mode==4){
                    v.x = acc[mt][nt][h2*2+0] + addv;
                    v.y = acc[mt][nt][h2*2+1] + addv;
                } else {
                    v.x = f2tf(acc[mt][nt][h2*2+0] + addv);
                    v.y = f2tf(acc[mt][nt][h2*2+1] + addv);
                }
                *(float2*)&C[(size_t)r*Sdim + col] = v;
            }
        }
    }
}

// ============ scores: scT[j,i]=(K_j.Q_i)/8, A=Kt permuted, + chunk max ======
// tile 128(j) x 64(i), K=64(c). grid (S/64, S/128, B*H).
__global__ __launch_bounds__(256) void gemm_sc_mma()
{
    __shared__ float As[2][128*16];
    __shared__ float Bs[2][16][72];
    int bh = blockIdx.z;
    int m0 = blockIdx.y*128;   // j
    int n0 = blockIdx.x*64;    // i
    if(n0 >= m0+128) return;
    const float* Kt = g_kt + ((size_t)bh*Sdim)*DHdim;
    const float* Qp = g_q  + (size_t)bh*DHdim*Sdim;

    int tid = threadIdx.x, lane = tid&31, wid = tid>>5;
    int wm = wid&1, wn = wid>>1;
    int am = tid>>2, akq = (tid&3)*4, ap = akq>>2;
    int bc = tid>>4, biq = (tid&15)*4;
    int rA = lane>>2, cL = lane&3;

    float4 pa0 = *(const float4*)&Kt[(size_t)(m0+am)*DHdim + akq];
    float4 pa1 = *(const float4*)&Kt[(size_t)(m0+am+64)*DHdim + akq];
    float4 pb0 = *(const float4*)&Qp[(size_t)bc*Sdim + n0+biq];

    float acc[4][2][4];
    #pragma unroll
    for(int i=0;i<4;i++)
      #pragma unroll
      for(int j=0;j<2;j++)
        #pragma unroll
        for(int k=0;k<4;k++) acc[i][j][k]=0.f;

    int st = 0;
    for(int k0=0;;){
        As[st][aswz(am,     0+ap)] = pa0.x;
        As[st][aswz(am,     4+ap)] = pa0.y;
        As[st][aswz(am,     8+ap)] = pa0.z;
        As[st][aswz(am,    12+ap)] = pa0.w;
        As[st][aswz(am+64,  0+ap)] = pa1.x;
        As[st][aswz(am+64,  4+ap)] = pa1.y;
        As[st][aswz(am+64,  8+ap)] = pa1.z;
        As[st][aswz(am+64, 12+ap)] = pa1.w;
        *(float4*)&Bs[st][bc][biq] = pb0;
        __syncthreads();
        k0 += 16;
        bool more = (k0 < 64);
        if(more){
            pa0 = *(const float4*)&Kt[(size_t)(m0+am)*DHdim + k0+akq];
            pa1 = *(const float4*)&Kt[(size_t)(m0+am+64)*DHdim + k0+akq];
            pb0 = *(const float4*)&Qp[(size_t)(k0+bc)*Sdim + n0+biq];
        }
        unsigned bf0[2][2], bf8[2][2];
        #pragma unroll
        for(int nt=0;nt<2;nt++){
            int n = wn*16 + nt*8 + rA;
            bf0[nt][0] = __float_as_uint(Bs[st][cL   ][n]);
            bf0[nt][1] = __float_as_uint(Bs[st][cL+4 ][n]);
            bf8[nt][0] = __float_as_uint(Bs[st][cL+8 ][n]);
            bf8[nt][1] = __float_as_uint(Bs[st][cL+12][n]);
        }
        #pragma unroll
        for(int mt=0;mt<4;mt++){
            int m = wm*64 + mt*16 + rA;
            float4 a1 = *(const float4*)&As[st][aswz(m,   4*cL)];
            float4 a2 = *(const float4*)&As[st][aswz(m+8, 4*cL)];
            unsigned af0[4] = {__float_as_uint(a1.x), __float_as_uint(a2.x),
                               __float_as_uint(a1.y), __float_as_uint(a2.y)};
            unsigned af8[4] = {__float_as_uint(a1.z), __float_as_uint(a2.z),
                               __float_as_uint(a1.w), __float_as_uint(a2.w)};
            #pragma unroll
            for(int nt=0;nt<2;nt++){
                mma8(acc[mt][nt], af0, bf0[nt]);
                mma8(acc[mt][nt], af8, bf8[nt]);
            }
        }
        st ^= 1;
        if(!more) break;
    }

    float* Cp = g_sc + (size_t)bh*Sdim*Sdim;
    #pragma unroll
    for(int mt=0;mt<4;mt++){
        #pragma unroll
        for(int h2=0;h2<2;h2++){
            int r = m0 + wm*64 + mt*16 + rA + h2*8;
            float vmax = -1e30f;
            #pragma unroll
            for(int nt=0;nt<2;nt++){
                int col = n0 + wn*16 + nt*8 + 2*cL;
                float2 v;
                v.x = acc[mt][nt][h2*2+0]*0.125f;
                v.y = acc[mt][nt][h2*2+1]*0.125f;
                if(col   <= r) vmax = fmaxf(vmax, v.x);
                if(col+1 <= r) vmax = fmaxf(vmax, v.y);
                *(float2*)&Cp[(size_t)r*Sdim + col] = v;
            }
            // quad-reduce over lane&3 -> 16-wide chunk max
            vmax = fmaxf(vmax, __shfl_xor_sync(0xffffffffu, vmax, 1));
            vmax = fmaxf(vmax, __shfl_xor_sync(0xffffffffu, vmax, 2));
            if(cL==0)
                g_pmax[(((size_t)bh<<10) + r)*64 + (n0>>4) + wn] = vmax;
        }
    }
}

// ============ softmax: max from g_pmax, one exp pass ========================
__global__ void k_softmax()
{
    int j = blockIdx.x, bh = blockIdx.y;
    float* row = g_sc + ((size_t)bh*Sdim + j)*Sdim;
    const float* pm = g_pmax + (((size_t)bh<<10) + j)*64;
    int n = j+1;
    int nc = (j>>4) + 1;
    int tid = threadIdx.x, lane = tid&31, wrp = tid>>5;
    __shared__ float red[8];
    float m = -1e30f;
    for(int c=tid;c<nc;c+=256) m = fmaxf(m, pm[c]);
    m = warp_max(m);
    if(lane==0) red[wrp]=m;
    __syncthreads();
    if(wrp==0){
        float t = (lane<8) ? red[lane] : -1e30f;
        t = warp_max(t);
        if(lane==0) red[0]=t;
    }
    __syncthreads();
    float M = red[0];
    __syncthreads();
    float s = 0.f;
    for(int i=tid;i<n;i+=256){
        float e = __expf(row[i]-M);
        row[i] = f2tf(e);
        s += e;
    }
    s = warp_sum(s);
    if(lane==0) red[wrp]=s;
    __syncthreads();
    if(wrp==0){
        float t = (lane<8) ? red[lane] : 0.f;
        t = warp_sum(t);
        if(lane==0) g_rinv[(size_t)bh*Sdim + j] = 1.0f/t;
    }
}

// ============ AV: A=P permuted, B=Vt. cat[c][j] with rinv ===================
// tile 128(j) x 64(c). grid (S/128, B*H).
__global__ __launch_bounds__(256) void gemm_av_mma()
{
    __shared__ float As[2][128*16];
    __shared__ float Bs[2][16][72];
    int bh = blockIdx.y; int b = bh>>3, h = bh&7;
    int m0 = blockIdx.x*128;
    const float* P  = g_sc + (size_t)bh*Sdim*Sdim;
    const float* Vt = g_vt + ((size_t)bh*Sdim)*DHdim;

    int tid = threadIdx.x, lane = tid&31, wid = tid>>5;
    int wm = wid&1, wn = wid>>1;
    int am = tid>>2, akq = (tid&3)*4, ap = akq>>2;
    int bk = tid>>4, bnq = (tid&15)*4;
    int rA = lane>>2, cL = lane&3;

    int j1 = m0+am, j2 = m0+am+64;
    float4 pa0 = *(const float4*)&P[(size_t)j1*Sdim + akq];
    float4 pa1 = *(const float4*)&P[(size_t)j2*Sdim + akq];
    {
        int i0 = akq;
        if(i0+0>j1) pa0.x=0.f; if(i0+1>j1) pa0.y=0.f;
        if(i0+2>j1) pa0.z=0.f; if(i0+3>j1) pa0.w=0.f;
    }
    float4 pb0 = *(const float4*)&Vt[(size_t)bk*DHdim + bnq];

    float acc[4][2][4];
    #pragma unroll
    for(int i=0;i<4;i++)
      #pragma unroll
      for(int j=0;j<2;j++)
        #pragma unroll
        for(int k=0;k<4;k++) acc[i][j][k]=0.f;

    int st = 0;
    int kmax = m0 + 128;
    for(int k0=0;;){
        As[st][aswz(am,     0+ap)] = pa0.x;
        As[st][aswz(am,     4+ap)] = pa0.y;
        As[st][aswz(am,     8+ap)] = pa0.z;
        As[st][aswz(am,    12+ap)] = pa0.w;
        As[st][aswz(am+64,  0+ap)] = pa1.x;
        As[st][aswz(am+64,  4+ap)] = pa1.y;
        As[st][aswz(am+64,  8+ap)] = pa1.z;
        As[st][aswz(am+64, 12+ap)] = pa1.w;
        *(float4*)&Bs[st][bk][bnq] = pb0;
        __syncthreads();
        k0 += 16;
        bool more = (k0 < kmax);
        if(more){
            int i0 = k0 + akq;
            pa0 = *(const float4*)&P[(size_t)j1*Sdim + i0];
            pa1 = *(const float4*)&P[(size_t)j2*Sdim + i0];
            if(i0+0>j1) pa0.x=0.f; if(i0+1>j1) pa0.y=0.f;
            if(i0+2>j1) pa0.z=0.f; if(i0+3>j1) pa0.w=0.f;
            if(i0+0>j2) pa1.x=0.f; if(i0+1>j2) pa1.y=0.f;
            if(i0+2>j2) pa1.z=0.f; if(i0+3>j2) pa1.w=0.f;
            pb0 = *(const float4*)&Vt[(size_t)(k0+bk)*DHdim + bnq];
        }
        unsigned bf0[2][2], bf8[2][2];
        #pragma unroll
        for(int nt=0;nt<2;nt++){
            int n = wn*16 + nt*8 + rA;
            bf0[nt][0] = __float_as_uint(Bs[st][cL   ][n]);
            bf0[nt][1] = __float_as_uint(Bs[st][cL+4 ][n]);
            bf8[nt][0] = __float_as_uint(Bs[st][cL+8 ][n]);
            bf8[nt][1] = __float_as_uint(Bs[st][cL+12][n]);
        }
        #pragma unroll
        for(int mt=0;mt<4;mt++){
            int m = wm*64 + mt*16 + rA;
            float4 a1 = *(const float4*)&As[st][aswz(m,   4*cL)];
            float4 a2 = *(const float4*)&As[st][aswz(m+8, 4*cL)];
            unsigned af0[4] = {__float_as_uint(a1.x), __float_as_uint(a2.x),
                               __float_as_uint(a1.y), __float_as_uint(a2.y)};
            unsigned af8[4] = {__float_as_uint(a1.z), __float_as_uint(a2.z),
                               __float_as_uint(a1.w), __float_as_uint(a2.w)};
            #pragma unroll
            for(int nt=0;nt<2;nt++){
                mma8(acc[mt][nt], af0, bf0[nt]);
                mma8(acc[mt][nt], af8, bf8[nt]);
            }
        }
        st ^= 1;
        if(!more) break;
    }

    float* catp = g_cat + ((size_t)b*Ddim + h*64)*Sdim;
    #pragma unroll
    for(int mt=0;mt<4;mt++){
        #pragma unroll
        for(int h2=0;h2<2;h2++){
            int r = m0 + wm*64 + mt*16 + rA + h2*8;   // j
            float rv = g_rinv[(size_t)bh*Sdim + r];
            #pragma unroll
            for(int nt=0;nt<2;nt++){
                int c = wn*16 + nt*8 + 2*cL;
                catp[(size_t)c*Sdim + r]     = f2tf(acc[mt][nt][h2*2+0]*rv);
                catp[(size_t)(c+1)*Sdim + r] = f2tf(acc[mt][nt][h2*2+1]*rv);
            }
        }
    }
}

// ============ residual + LN2 ================================================
__global__ void k_ln2(float* __restrict__ out, const float* __restrict__ g2,
                      const float* __restrict__ b2)
{
    __shared__ float sm[16][513];
    int b = blockIdx.y, s0 = blockIdx.x*16;
    int tid = threadIdx.x;
    const float* convp = g_conv + (size_t)b*Ddim*Sdim;
    float* op = out + (size_t)b*Ddim*Sdim;
    #pragma unroll
    for(int it=0; it<16; ++it){
        int idx = it*512 + tid; int sl = idx & 15, dd = idx >> 4;
        size_t a = (size_t)dd*Sdim + s0 + sl;
        sm[sl][dd] = op[a] + convp[a];
    }
    __syncthreads();
    int wrp = tid>>5, lane = tid&31;
    {
        float sum=0.f, sq=0.f;
        #pragma unroll
        for(int k=0;k<16;k++){ float x = sm[wrp][lane + k*32]; sum+=x; sq+=x*x; }
        sum = warp_sum(sum); sq = warp_sum(sq);
        float mean = sum*(1.0f/512.0f);
        float var  = (sq - 512.0f*mean*mean)*(1.0f/511.0f);
        float inv  = rsqrtf(var + 1e-5f);
        float gg = g2[s0+wrp], bb = b2[s0+wrp];
        #pragma unroll
        for(int k=0;k<16;k++){
            int dd = lane + k*32;
            sm[wrp][dd] = (sm[wrp][dd]-mean)*inv*gg + bb;
        }
    }
    __syncthreads();
    #pragma unroll
    for(int it=0; it<16; ++it){
        int idx = it*512 + tid; int sl = idx & 15, dd = idx >> 4;
        op[(size_t)dd*Sdim + s0 + sl] = sm[sl][dd];
    }
}

// ============================================================================
extern "C" void kernel_launch(void* const* d_in, const int* in_sizes, int n_in,
                              void* d_out, int out_size)
{
    const float* ts     = (const float*)d_in[0];
    const int*   te     = (const int*)  d_in[1];
    const float* conv_w = (const float*)d_in[2];
    const float* conv_b = (const float*)d_in[3];
    const float* pe     = (const float*)d_in[4];
    const float* tsemb  = (const float*)d_in[5];
    const float* g1     = (const float*)d_in[6];
    const float* b1     = (const float*)d_in[7];
    const float* Mw     = (const float*)d_in[8];
    const float* Wq     = (const float*)d_in[9];
    const float* Wk     = (const float*)d_in[10];
    const float* Wv     = (const float*)d_in[11];
    const float* Wo     = (const float*)d_in[12];
    const float* bo     = (const float*)d_in[13];
    const float* g2     = (const float*)d_in[14];
    const float* b2     = (const float*)d_in[15];
    float* out = (float*)d_out;

    dim3 gg(Sdim/128, Ddim/128, Bdim);   // (8,4,16)
    k_prep     <<<5*262144/1024, 256>>>(Mw, Wq, Wk, Wv, Wo);
    k_front    <<<dim3(Sdim/16, Bdim), 512>>>(ts, conv_w, conv_b, pe, g1, b1);
    gemm_tf32  <<<gg, 256>>>(0,   0,  tsemb, te, 0);
    gemm_tf32  <<<gg, 256>>>(0,   0,  0,     0,  1);
    gemm_tf32  <<<gg, 256>>>(0,   0,  0,     0,  2);
    gemm_tf32  <<<gg, 256>>>(0,   0,  0,     0,  3);
    gemm_sc_mma<<<dim3(Sdim/64, Sdim/128, Bdim*Hdim), 256>>>();
    k_softmax  <<<dim3(Sdim, Bdim*Hdim), 256>>>();
    gemm_av_mma<<<dim3(Sdim/128, Bdim*Hdim), 256>>>();
    gemm_tf32  <<<gg, 256>>>(out, bo, 0,     0,  4);
    k_ln2      <<<dim3(Sdim/16, Bdim), 512>>>(out, g2, b2);
}